// round 4
// baseline (speedup 1.0000x reference)
#include <cuda_runtime.h>
#include <cuda_bf16.h>
#include <cstddef>

#define TPB      512
#define NFFT     4096
#define CST      4356                 // per-column smem stride (float2)
#define PHYS(i)  ((i) + ((i) >> 4))   // data padding: every 16 elements
#define PHYT(i)  ((i) + ((i) >> 4) + ((i) >> 6))  // twiddle-table padding
#define TWN      256
#define TWSZ     288                  // > PHYT(255) = 273
#define PERM16(m) ((((m) & 3) << 2) | ((m) >> 2))

__device__ __forceinline__ float2 cmul(float2 a, float2 b) {
    return make_float2(fmaf(a.x, b.x, -a.y * b.y), fmaf(a.x, b.y, a.y * b.x));
}
// a * conj(b)
__device__ __forceinline__ float2 cmulc(float2 a, float2 b) {
    return make_float2(fmaf(a.x, b.x, a.y * b.y), fmaf(a.y, b.x, -a.x * b.y));
}

__device__ __forceinline__ void dft4(float2 &a, float2 &b, float2 &c, float2 &d) {
    float2 t0 = make_float2(a.x + c.x, a.y + c.y);
    float2 t1 = make_float2(a.x - c.x, a.y - c.y);
    float2 t2 = make_float2(b.x + d.x, b.y + d.y);
    float2 t3 = make_float2(b.x - d.x, b.y - d.y);
    a = make_float2(t0.x + t2.x, t0.y + t2.y);
    c = make_float2(t0.x - t2.x, t0.y - t2.y);
    b = make_float2(t1.x + t3.y, t1.y - t3.x);   // t1 - i*t3
    d = make_float2(t1.x - t3.y, t1.y + t3.x);   // t1 + i*t3
}

// 16-point forward DFT, natural input order. Output X[m] ends at slot PERM16(m).
__device__ __forceinline__ void dft16(float2 v[16]) {
    #pragma unroll
    for (int j0 = 0; j0 < 4; j0++) dft4(v[j0], v[j0 + 4], v[j0 + 8], v[j0 + 12]);
    const float C1 = 0.92387953251128675613f;   // cos(pi/8)
    const float S1 = 0.38268343236508977173f;   // sin(pi/8)
    const float C2 = 0.70710678118654752440f;   // sqrt(2)/2
    v[5]  = cmul(v[5],  make_float2( C1, -S1));
    v[9]  = cmul(v[9],  make_float2( C2, -C2));
    v[13] = cmul(v[13], make_float2( S1, -C1));
    v[6]  = cmul(v[6],  make_float2( C2, -C2));
    { float2 t = v[10]; v[10] = make_float2(t.y, -t.x); }
    v[14] = cmul(v[14], make_float2(-C2, -C2));
    v[7]  = cmul(v[7],  make_float2( S1, -C1));
    v[11] = cmul(v[11], make_float2(-C2, -C2));
    v[15] = cmul(v[15], make_float2(-C1,  S1));
    #pragma unroll
    for (int m0 = 0; m0 < 4; m0++) dft4(v[4*m0], v[4*m0+1], v[4*m0+2], v[4*m0+3]);
}

// Forward radix-16 DIF pass, sub-transform length L = 16*Q. One butterfly/thread.
// Twiddle powers by incremental chain (2 live regs) to fit 64-reg budget.
template <int LOG2Q>
__device__ __forceinline__ void fwd_pass16(float2 *sm, const float2 *tw, int tid) {
    const int Q  = 1 << LOG2Q;
    const int QP = Q + (Q >> 4);       // physical stride (Q multiple of 16)
    float2 *Bp = sm + (tid >> 8) * CST;
    int wi = tid & 255;
    int j  = wi & (Q - 1);
    int g  = wi >> LOG2Q;
    int p0 = PHYS(g * (16 * Q) + j);
    float2 v[16];
    #pragma unroll
    for (int m = 0; m < 16; m++) v[m] = Bp[p0 + m * QP];
    dft16(v);
    int e = j << (8 - LOG2Q);
    float2 w1 = tw[PHYT(e)];
    Bp[p0] = v[0];
    Bp[p0 + QP] = cmul(v[PERM16(1)], w1);
    float2 w = w1;
    #pragma unroll
    for (int m = 2; m < 16; m++) {
        w = cmul(w, w1);
        Bp[p0 + m * QP] = cmul(v[PERM16(m)], w);
    }
    __syncthreads();
}

// Inverse radix-16 DIT pass (conjugate twiddles). One butterfly/thread.
// conj-twiddle applied as elements load: conj(raw * conj(w^m)) = cmulc(w^m, raw).
template <int LOG2Q>
__device__ __forceinline__ void inv_pass16(float2 *sm, const float2 *tw, int tid) {
    const int Q  = 1 << LOG2Q;
    const int QP = Q + (Q >> 4);
    float2 *Bp = sm + (tid >> 8) * CST;
    int wi = tid & 255;
    int j  = wi & (Q - 1);
    int g  = wi >> LOG2Q;
    int p0 = PHYS(g * (16 * Q) + j);
    int e = j << (8 - LOG2Q);
    float2 w1 = tw[PHYT(e)];
    float2 v[16];
    {
        float2 u = Bp[p0];
        v[0] = make_float2(u.x, -u.y);
    }
    v[1] = cmulc(w1, Bp[p0 + QP]);
    float2 w = w1;
    #pragma unroll
    for (int m = 2; m < 16; m++) {
        w = cmul(w, w1);
        v[m] = cmulc(w, Bp[p0 + m * QP]);
    }
    dft16(v);
    #pragma unroll
    for (int m = 0; m < 16; m++) {
        float2 u = v[PERM16(m)];
        Bp[p0 + m * QP] = make_float2(u.x, -u.y);
    }
    __syncthreads();
}

// Digit reversal for radices [16,16,16] DIF order (12-bit index).
__device__ __forceinline__ int rev16(int k) {
    return ((k & 15) << 8) | (k & 0xF0) | (k >> 8);
}

// Unpack -> filter -> repack for one (k, 4096-k) pair, in digit-reversed smem.
__device__ __forceinline__ void filter_pair(float2 *Bp, const float2 *__restrict__ Hb, int k) {
    int km = 4096 - k;
    int pk = PHYS(rev16(k));
    int pm = PHYS(rev16(km));
    float2 Zk = Bp[pk];
    float2 Zm = Bp[pm];
    float2 Xe = make_float2(0.5f * (Zk.x + Zm.x), 0.5f * (Zk.y - Zm.y));
    float2 u  = make_float2(Zk.x - Zm.x, Zk.y + Zm.y);
    float2 Xo = make_float2(0.5f * u.y, -0.5f * u.x);
    float s, co;
    sincospif((float)k * (1.0f / 4096.0f), &s, &co);
    float2 W = make_float2(co, -s);               // e^{-2*pi*i*k/8192}
    float2 WXo = cmul(W, Xo);
    float2 Xk = make_float2(Xe.x + WXo.x, Xe.y + WXo.y);
    float2 Xm = make_float2(Xe.x - WXo.x, -(Xe.y - WXo.y));   // conj(Xe - W*Xo)
    float2 Yk = cmul(Xk, __ldg(Hb + k));
    float2 Ym = cmul(Xm, __ldg(Hb + km));
    float2 Ye = make_float2(0.5f * (Yk.x + Ym.x), 0.5f * (Yk.y - Ym.y));
    float2 u2 = make_float2(Yk.x - Ym.x, Yk.y + Ym.y);
    float2 Yo = cmulc(make_float2(0.5f * u2.x, 0.5f * u2.y), W);
    Bp[pk] = make_float2(Ye.x - Yo.y, Ye.y + Yo.x);
    Bp[pm] = make_float2(Ye.x + Yo.y, Yo.x - Ye.y);
}

__global__ __launch_bounds__(TPB, 2)
void _ScaleFFTFilter_45380624449589_kernel(const float *__restrict__ x,
                                           const float2 *__restrict__ H2,
                                           float *__restrict__ y) {
    extern __shared__ float2 smem_raw[];
    float2 *sm = smem_raw;             // 2 columns * CST
    float2 *tw = smem_raw + 2 * CST;   // padded twiddle table

    const int tid = threadIdx.x;
    const int fg  = blockIdx.x >> 3;   // feature group (0..255)
    const int b   = blockIdx.x & 7;    // batch (0..7)
    const int f0  = fg * 2;

    // twiddle table: tw[m] = e^{-2*pi*i*m/4096}, m < 256
    if (tid < TWN) {
        float s, co;
        sincospif((float)tid * (1.0f / 2048.0f), &s, &co);
        tw[PHYT(tid)] = make_float2(co, -s);
    }

    // Load + pack: z_c[n] = x[b, 2n, f0+c] + i*x[b, 2n+1, f0+c]
    const float *xb = x + ((size_t)b * 8192) * 512 + f0;
    for (int it = 0; it < 16; it++) {
        int idx = it * TPB + tid;      // 0..8191
        int cc = idx & 1;
        int n  = idx >> 1;
        float xr = __ldg(xb + (size_t)(2 * n) * 512 + cc);
        float xi = __ldg(xb + (size_t)(2 * n + 1) * 512 + cc);
        sm[cc * CST + PHYS(n)] = make_float2(xr, xi);
    }
    __syncthreads();

    // ---- forward FFT (DIF radix-16 x3): output digit-reversed ----
    fwd_pass16<8>(sm, tw, tid);
    fwd_pass16<4>(sm, tw, tid);
    {   // final radix-16 blocks (no twiddles): 512 blocks, 1/thread
        float2 *Bp = sm + (tid >> 8) * CST;
        int p0 = PHYS((tid & 255) * 16);
        float2 v[16];
        #pragma unroll
        for (int j = 0; j < 16; j++) v[j] = Bp[p0 + j];
        dft16(v);
        #pragma unroll
        for (int m = 0; m < 16; m++) Bp[p0 + m] = v[PERM16(m)];
    }
    __syncthreads();

    // ---- unpack -> filter -> repack (digit-reversed domain) ----
    for (int it = 0; it < 8; it++) {
        int idx = it * TPB + tid;      // 0..4095
        int cc = idx >> 11;
        int q  = idx & 2047;
        float2 *Bp = sm + cc * CST;
        const float2 *Hb = H2 + (size_t)(f0 + cc) * 4097;
        if (q == 0) {
            float2 z0 = Bp[PHYS(0)];
            float X0 = z0.x + z0.y;
            float XN = z0.x - z0.y;
            float Y0 = X0 * __ldg(Hb + 0).x;
            float YN = XN * __ldg(Hb + 4096).x;
            Bp[PHYS(0)] = make_float2(0.5f * (Y0 + YN), 0.5f * (Y0 - YN));
        } else {
            // digit-shuffled enumeration of 1..2047: rev16(k) thread-consecutive
            int k = ((q & 7) << 8) | (((q >> 3) & 15) << 4) | (q >> 7);
            filter_pair(Bp, Hb, k);
        }
    }
    if (tid < 2) {   // self-paired bin k = 2048
        filter_pair(sm + tid * CST, H2 + (size_t)(f0 + tid) * 4097, 2048);
    }
    __syncthreads();

    // ---- inverse FFT (DIT radix-16 x3): digit-reversed in, natural out ----
    {
        float2 *Bp = sm + (tid >> 8) * CST;
        int p0 = PHYS((tid & 255) * 16);
        float2 v[16];
        #pragma unroll
        for (int j = 0; j < 16; j++) {
            float2 u = Bp[p0 + j];
            v[j] = make_float2(u.x, -u.y);
        }
        dft16(v);
        #pragma unroll
        for (int m = 0; m < 16; m++) {
            float2 u = v[PERM16(m)];
            Bp[p0 + m] = make_float2(u.x, -u.y);
        }
    }
    __syncthreads();
    inv_pass16<4>(sm, tw, tid);
    inv_pass16<8>(sm, tw, tid);

    // ---- unpack to real output (scale 1/4096) ----
    float *yb = y + ((size_t)b * 8192) * 512 + f0;
    const float SC = 1.0f / 4096.0f;
    for (int it = 0; it < 16; it++) {
        int idx = it * TPB + tid;
        int cc = idx & 1;
        int n  = idx >> 1;
        float2 v = sm[cc * CST + PHYS(n)];
        yb[(size_t)(2 * n) * 512 + cc]     = v.x * SC;
        yb[(size_t)(2 * n + 1) * 512 + cc] = v.y * SC;
    }
}

extern "C" void kernel_launch(void* const* d_in, const int* in_sizes, int n_in,
                              void* d_out, int out_size) {
    (void)in_sizes; (void)n_in; (void)out_size;
    const float  *x  = (const float*)d_in[0];
    const float2 *H2 = (const float2*)d_in[1];
    float        *y  = (float*)d_out;

    const size_t smem_bytes = (size_t)(2 * CST + TWSZ) * sizeof(float2);  // ~70.3 KB
    cudaFuncSetAttribute(_ScaleFFTFilter_45380624449589_kernel,
                         cudaFuncAttributeMaxDynamicSharedMemorySize,
                         (int)smem_bytes);
    _ScaleFFTFilter_45380624449589_kernel<<<2048, TPB, smem_bytes>>>(x, H2, y);
}

// round 5
// speedup vs baseline: 1.3806x; 1.3806x over previous
#include <cuda_runtime.h>
#include <cuda_bf16.h>
#include <cstddef>

#define TPB      1024
#define NFFT     4096
#define CST      4356                 // per-column smem stride (float2)
#define PHYS(i)  ((i) + ((i) >> 4))   // data padding: every 16 elements
#define PHYT(i)  ((i) + ((i) >> 4) + ((i) >> 6))  // twiddle-table padding
#define TWN      256
#define TWSZ     288                  // > PHYT(255) = 273
#define PERM16(m) ((((m) & 3) << 2) | ((m) >> 2))

__device__ __forceinline__ float2 cmul(float2 a, float2 b) {
    return make_float2(fmaf(a.x, b.x, -a.y * b.y), fmaf(a.x, b.y, a.y * b.x));
}
// a * conj(b)
__device__ __forceinline__ float2 cmulc(float2 a, float2 b) {
    return make_float2(fmaf(a.x, b.x, a.y * b.y), fmaf(a.y, b.x, -a.x * b.y));
}

__device__ __forceinline__ void dft4(float2 &a, float2 &b, float2 &c, float2 &d) {
    float2 t0 = make_float2(a.x + c.x, a.y + c.y);
    float2 t1 = make_float2(a.x - c.x, a.y - c.y);
    float2 t2 = make_float2(b.x + d.x, b.y + d.y);
    float2 t3 = make_float2(b.x - d.x, b.y - d.y);
    a = make_float2(t0.x + t2.x, t0.y + t2.y);
    c = make_float2(t0.x - t2.x, t0.y - t2.y);
    b = make_float2(t1.x + t3.y, t1.y - t3.x);   // t1 - i*t3
    d = make_float2(t1.x - t3.y, t1.y + t3.x);   // t1 + i*t3
}

// 16-point forward DFT, natural input order. Output X[m] ends at slot PERM16(m).
__device__ __forceinline__ void dft16(float2 v[16]) {
    #pragma unroll
    for (int j0 = 0; j0 < 4; j0++) dft4(v[j0], v[j0 + 4], v[j0 + 8], v[j0 + 12]);
    const float C1 = 0.92387953251128675613f;   // cos(pi/8)
    const float S1 = 0.38268343236508977173f;   // sin(pi/8)
    const float C2 = 0.70710678118654752440f;   // sqrt(2)/2
    v[5]  = cmul(v[5],  make_float2( C1, -S1));
    v[9]  = cmul(v[9],  make_float2( C2, -C2));
    v[13] = cmul(v[13], make_float2( S1, -C1));
    v[6]  = cmul(v[6],  make_float2( C2, -C2));
    { float2 t = v[10]; v[10] = make_float2(t.y, -t.x); }
    v[14] = cmul(v[14], make_float2(-C2, -C2));
    v[7]  = cmul(v[7],  make_float2( S1, -C1));
    v[11] = cmul(v[11], make_float2(-C2, -C2));
    v[15] = cmul(v[15], make_float2(-C1,  S1));
    #pragma unroll
    for (int m0 = 0; m0 < 4; m0++) dft4(v[4*m0], v[4*m0+1], v[4*m0+2], v[4*m0+3]);
}

// Middle forward radix-16 DIF pass, Q = 16 (sub-transform length 256).
__device__ __forceinline__ void fwd_pass_mid(float2 *sm, const float2 *tw, int tid) {
    const int QP = 17;                 // PHYS stride for Q=16
    float2 *Bp = sm + (tid >> 8) * CST;
    int wi = tid & 255;
    int j  = wi & 15;
    int g  = wi >> 4;
    int p0 = PHYS(g * 256 + j);
    float2 v[16];
    #pragma unroll
    for (int m = 0; m < 16; m++) v[m] = Bp[p0 + m * QP];
    dft16(v);
    float2 w1 = tw[PHYT(j << 4)];
    Bp[p0] = v[0];
    Bp[p0 + QP] = cmul(v[PERM16(1)], w1);
    float2 w = w1;
    #pragma unroll
    for (int m = 2; m < 16; m++) {
        w = cmul(w, w1);
        Bp[p0 + m * QP] = cmul(v[PERM16(m)], w);
    }
    __syncthreads();
}

// Middle inverse radix-16 DIT pass, Q = 16.
__device__ __forceinline__ void inv_pass_mid(float2 *sm, const float2 *tw, int tid) {
    const int QP = 17;
    float2 *Bp = sm + (tid >> 8) * CST;
    int wi = tid & 255;
    int j  = wi & 15;
    int g  = wi >> 4;
    int p0 = PHYS(g * 256 + j);
    float2 w1 = tw[PHYT(j << 4)];
    float2 v[16];
    {
        float2 u = Bp[p0];
        v[0] = make_float2(u.x, -u.y);
    }
    v[1] = cmulc(w1, Bp[p0 + QP]);
    float2 w = w1;
    #pragma unroll
    for (int m = 2; m < 16; m++) {
        w = cmul(w, w1);
        v[m] = cmulc(w, Bp[p0 + m * QP]);
    }
    dft16(v);
    #pragma unroll
    for (int m = 0; m < 16; m++) {
        float2 u = v[PERM16(m)];
        Bp[p0 + m * QP] = make_float2(u.x, -u.y);
    }
    __syncthreads();
}

// Digit reversal for radices [16,16,16] DIF order (12-bit index).
__device__ __forceinline__ int rev16(int k) {
    return ((k & 15) << 8) | (k & 0xF0) | (k >> 8);
}

// Unpack -> filter -> repack for one (k, 4096-k) pair, in digit-reversed smem.
__device__ __forceinline__ void filter_pair(float2 *Bp, const float2 *__restrict__ Hb, int k) {
    int km = 4096 - k;
    int pk = PHYS(rev16(k));
    int pm = PHYS(rev16(km));
    float2 Zk = Bp[pk];
    float2 Zm = Bp[pm];
    float2 Xe = make_float2(0.5f * (Zk.x + Zm.x), 0.5f * (Zk.y - Zm.y));
    float2 u  = make_float2(Zk.x - Zm.x, Zk.y + Zm.y);
    float2 Xo = make_float2(0.5f * u.y, -0.5f * u.x);
    float s, co;
    sincospif((float)k * (1.0f / 4096.0f), &s, &co);
    float2 W = make_float2(co, -s);               // e^{-2*pi*i*k/8192}
    float2 WXo = cmul(W, Xo);
    float2 Xk = make_float2(Xe.x + WXo.x, Xe.y + WXo.y);
    float2 Xm = make_float2(Xe.x - WXo.x, -(Xe.y - WXo.y));   // conj(Xe - W*Xo)
    float2 Yk = cmul(Xk, __ldg(Hb + k));
    float2 Ym = cmul(Xm, __ldg(Hb + km));
    float2 Ye = make_float2(0.5f * (Yk.x + Ym.x), 0.5f * (Yk.y - Ym.y));
    float2 u2 = make_float2(Yk.x - Ym.x, Yk.y + Ym.y);
    float2 Yo = cmulc(make_float2(0.5f * u2.x, 0.5f * u2.y), W);
    Bp[pk] = make_float2(Ye.x - Yo.y, Ye.y + Yo.x);
    Bp[pm] = make_float2(Ye.x + Yo.y, Yo.x - Ye.y);
}

__global__ __launch_bounds__(TPB, 1)
void _ScaleFFTFilter_45380624449589_kernel(const float *__restrict__ x,
                                           const float2 *__restrict__ H2,
                                           float *__restrict__ y) {
    extern __shared__ float2 smem_raw[];
    float2 *sm = smem_raw;             // 4 columns * CST
    float2 *tw = smem_raw + 4 * CST;   // padded twiddle table

    const int tid = threadIdx.x;
    const int fg  = blockIdx.x >> 3;   // feature group (0..127)
    const int b   = blockIdx.x & 7;    // batch (0..7)
    const int f0  = fg * 4;

    // twiddle table: tw[m] = e^{-2*pi*i*m/4096}, m < 256
    if (tid < TWN) {
        float s, co;
        sincospif((float)tid * (1.0f / 2048.0f), &s, &co);
        tw[PHYT(tid)] = make_float2(co, -s);
    }
    __syncthreads();

    // ---- fused: global load + pack + first fwd radix-16 pass (Q=256) ----
    // Lane map (cc = tid&3, j = tid>>2): warp covers 4 cols x 8 rows ->
    // global reads hit 8 distinct rows, 16B/sector; smem stores conflict-free.
    {
        const int cc = tid & 3;
        const int j  = tid >> 2;       // 0..255
        const float *xc = x + ((size_t)b * 8192) * 512 + f0 + cc;
        float2 v[16];
        #pragma unroll
        for (int m = 0; m < 16; m++) {
            size_t row = (size_t)2 * (j + m * 256);
            v[m] = make_float2(__ldg(xc + row * 512), __ldg(xc + (row + 1) * 512));
        }
        dft16(v);
        float2 *Bp = sm + cc * CST;
        int p0 = PHYS(j);
        float2 w1 = tw[PHYT(j)];
        Bp[p0] = v[0];
        Bp[p0 + 272] = cmul(v[PERM16(1)], w1);
        float2 w = w1;
        #pragma unroll
        for (int m = 2; m < 16; m++) {
            w = cmul(w, w1);
            Bp[p0 + m * 272] = cmul(v[PERM16(m)], w);
        }
    }
    __syncthreads();

    fwd_pass_mid(sm, tw, tid);

    {   // final forward radix-16 blocks (no twiddles)
        float2 *Bp = sm + (tid >> 8) * CST;
        int p0 = PHYS((tid & 255) * 16);
        float2 v[16];
        #pragma unroll
        for (int j = 0; j < 16; j++) v[j] = Bp[p0 + j];
        dft16(v);
        #pragma unroll
        for (int m = 0; m < 16; m++) Bp[p0 + m] = v[PERM16(m)];
    }
    __syncthreads();

    // ---- unpack -> filter -> repack (digit-reversed domain) ----
    for (int it = 0; it < 8; it++) {
        int idx = it * TPB + tid;      // 0..8191
        int cc = idx >> 11;
        int q  = idx & 2047;
        float2 *Bp = sm + cc * CST;
        const float2 *Hb = H2 + (size_t)(f0 + cc) * 4097;
        if (q == 0) {
            float2 z0 = Bp[PHYS(0)];
            float X0 = z0.x + z0.y;
            float XN = z0.x - z0.y;
            float Y0 = X0 * __ldg(Hb + 0).x;
            float YN = XN * __ldg(Hb + 4096).x;
            Bp[PHYS(0)] = make_float2(0.5f * (Y0 + YN), 0.5f * (Y0 - YN));
        } else {
            int k = ((q & 7) << 8) | (((q >> 3) & 15) << 4) | (q >> 7);
            filter_pair(Bp, Hb, k);
        }
    }
    if (tid < 4) {   // self-paired bin k = 2048
        filter_pair(sm + tid * CST, H2 + (size_t)(f0 + tid) * 4097, 2048);
    }
    __syncthreads();

    {   // first inverse radix-16 blocks (no twiddles)
        float2 *Bp = sm + (tid >> 8) * CST;
        int p0 = PHYS((tid & 255) * 16);
        float2 v[16];
        #pragma unroll
        for (int j = 0; j < 16; j++) {
            float2 u = Bp[p0 + j];
            v[j] = make_float2(u.x, -u.y);
        }
        dft16(v);
        #pragma unroll
        for (int m = 0; m < 16; m++) {
            float2 u = v[PERM16(m)];
            Bp[p0 + m] = make_float2(u.x, -u.y);
        }
    }
    __syncthreads();

    inv_pass_mid(sm, tw, tid);

    // ---- fused: last inverse pass (Q=256) + unpack + global store ----
    {
        const int cc = tid & 3;
        const int j  = tid >> 2;       // 0..255
        float2 *Bp = sm + cc * CST;
        int p0 = PHYS(j);
        float2 w1 = tw[PHYT(j)];
        float2 v[16];
        {
            float2 u = Bp[p0];
            v[0] = make_float2(u.x, -u.y);
        }
        v[1] = cmulc(w1, Bp[p0 + 272]);
        float2 w = w1;
        #pragma unroll
        for (int m = 2; m < 16; m++) {
            w = cmul(w, w1);
            v[m] = cmulc(w, Bp[p0 + m * 272]);
        }
        dft16(v);
        float *yc = y + ((size_t)b * 8192) * 512 + f0 + cc;
        const float SC = 1.0f / 4096.0f;
        #pragma unroll
        for (int m = 0; m < 16; m++) {
            float2 u = v[PERM16(m)];           // result = conj(u)
            size_t row = (size_t)2 * (j + m * 256);
            yc[row * 512]       = u.x * SC;
            yc[(row + 1) * 512] = -u.y * SC;
        }
    }
}

extern "C" void kernel_launch(void* const* d_in, const int* in_sizes, int n_in,
                              void* d_out, int out_size) {
    (void)in_sizes; (void)n_in; (void)out_size;
    const float  *x  = (const float*)d_in[0];
    const float2 *H2 = (const float2*)d_in[1];
    float        *y  = (float*)d_out;

    const size_t smem_bytes = (size_t)(4 * CST + TWSZ) * sizeof(float2);  // ~141.7 KB
    cudaFuncSetAttribute(_ScaleFFTFilter_45380624449589_kernel,
                         cudaFuncAttributeMaxDynamicSharedMemorySize,
                         (int)smem_bytes);
    _ScaleFFTFilter_45380624449589_kernel<<<1024, TPB, smem_bytes>>>(x, H2, y);
}

// round 6
// speedup vs baseline: 1.6094x; 1.1657x over previous
#include <cuda_runtime.h>
#include <cuda_bf16.h>
#include <cstddef>

#define TPB      1024
#define NFFT     4096
#define CST      4356                 // per-column smem stride (float2)
#define PHYS(i)  ((i) + ((i) >> 4))   // data padding: every 16 elements
#define PHYT(i)  ((i) + ((i) >> 4) + ((i) >> 6))  // twiddle-table padding
#define TWN      256
#define TWSZ     288                  // > PHYT(255) = 273
#define PERM16(m) ((((m) & 3) << 2) | ((m) >> 2))

// Scratch: H packed in filter-phase access order. H_pack[f][q] = (Hk, Hm),
// q the thread-linear pair index; slot 0 = (H0.re, HN.re, H2048.re, H2048.im).
__device__ float4 g_Hpack[512 * 2048];

__device__ __forceinline__ float2 cmul(float2 a, float2 b) {
    return make_float2(fmaf(a.x, b.x, -a.y * b.y), fmaf(a.x, b.y, a.y * b.x));
}
// a * conj(b)
__device__ __forceinline__ float2 cmulc(float2 a, float2 b) {
    return make_float2(fmaf(a.x, b.x, a.y * b.y), fmaf(a.y, b.x, -a.x * b.y));
}

__device__ __forceinline__ void dft4(float2 &a, float2 &b, float2 &c, float2 &d) {
    float2 t0 = make_float2(a.x + c.x, a.y + c.y);
    float2 t1 = make_float2(a.x - c.x, a.y - c.y);
    float2 t2 = make_float2(b.x + d.x, b.y + d.y);
    float2 t3 = make_float2(b.x - d.x, b.y - d.y);
    a = make_float2(t0.x + t2.x, t0.y + t2.y);
    c = make_float2(t0.x - t2.x, t0.y - t2.y);
    b = make_float2(t1.x + t3.y, t1.y - t3.x);   // t1 - i*t3
    d = make_float2(t1.x - t3.y, t1.y + t3.x);   // t1 + i*t3
}

// 16-point forward DFT, natural input order. Output X[m] ends at slot PERM16(m).
__device__ __forceinline__ void dft16(float2 v[16]) {
    #pragma unroll
    for (int j0 = 0; j0 < 4; j0++) dft4(v[j0], v[j0 + 4], v[j0 + 8], v[j0 + 12]);
    const float C1 = 0.92387953251128675613f;   // cos(pi/8)
    const float S1 = 0.38268343236508977173f;   // sin(pi/8)
    const float C2 = 0.70710678118654752440f;   // sqrt(2)/2
    v[5]  = cmul(v[5],  make_float2( C1, -S1));
    v[9]  = cmul(v[9],  make_float2( C2, -C2));
    v[13] = cmul(v[13], make_float2( S1, -C1));
    v[6]  = cmul(v[6],  make_float2( C2, -C2));
    { float2 t = v[10]; v[10] = make_float2(t.y, -t.x); }
    v[14] = cmul(v[14], make_float2(-C2, -C2));
    v[7]  = cmul(v[7],  make_float2( S1, -C1));
    v[11] = cmul(v[11], make_float2(-C2, -C2));
    v[15] = cmul(v[15], make_float2(-C1,  S1));
    #pragma unroll
    for (int m0 = 0; m0 < 4; m0++) dft4(v[4*m0], v[4*m0+1], v[4*m0+2], v[4*m0+3]);
}

// Middle forward radix-16 DIF pass, Q = 16 (sub-transform length 256).
__device__ __forceinline__ void fwd_pass_mid(float2 *sm, const float2 *tw, int tid) {
    const int QP = 17;                 // PHYS stride for Q=16
    float2 *Bp = sm + (tid >> 8) * CST;
    int wi = tid & 255;
    int j  = wi & 15;
    int g  = wi >> 4;
    int p0 = PHYS(g * 256 + j);
    float2 v[16];
    #pragma unroll
    for (int m = 0; m < 16; m++) v[m] = Bp[p0 + m * QP];
    dft16(v);
    float2 w1 = tw[PHYT(j << 4)];
    Bp[p0] = v[0];
    Bp[p0 + QP] = cmul(v[PERM16(1)], w1);
    float2 w = w1;
    #pragma unroll
    for (int m = 2; m < 16; m++) {
        w = cmul(w, w1);
        Bp[p0 + m * QP] = cmul(v[PERM16(m)], w);
    }
    __syncthreads();
}

// Middle inverse radix-16 DIT pass, Q = 16.
__device__ __forceinline__ void inv_pass_mid(float2 *sm, const float2 *tw, int tid) {
    const int QP = 17;
    float2 *Bp = sm + (tid >> 8) * CST;
    int wi = tid & 255;
    int j  = wi & 15;
    int g  = wi >> 4;
    int p0 = PHYS(g * 256 + j);
    float2 w1 = tw[PHYT(j << 4)];
    float2 v[16];
    {
        float2 u = Bp[p0];
        v[0] = make_float2(u.x, -u.y);
    }
    v[1] = cmulc(w1, Bp[p0 + QP]);
    float2 w = w1;
    #pragma unroll
    for (int m = 2; m < 16; m++) {
        w = cmul(w, w1);
        v[m] = cmulc(w, Bp[p0 + m * QP]);
    }
    dft16(v);
    #pragma unroll
    for (int m = 0; m < 16; m++) {
        float2 u = v[PERM16(m)];
        Bp[p0 + m * QP] = make_float2(u.x, -u.y);
    }
    __syncthreads();
}

// Digit reversal for radices [16,16,16] DIF order (12-bit index).
__device__ __forceinline__ int rev16(int k) {
    return ((k & 15) << 8) | (k & 0xF0) | (k >> 8);
}

// Unpack -> filter -> repack for one (k, 4096-k) pair, in digit-reversed smem.
__device__ __forceinline__ void filter_pair(float2 *Bp, float2 Hk, float2 Hm, int k) {
    int km = 4096 - k;
    int pk = PHYS(rev16(k));
    int pm = PHYS(rev16(km));
    float2 Zk = Bp[pk];
    float2 Zm = Bp[pm];
    float2 Xe = make_float2(0.5f * (Zk.x + Zm.x), 0.5f * (Zk.y - Zm.y));
    float2 u  = make_float2(Zk.x - Zm.x, Zk.y + Zm.y);
    float2 Xo = make_float2(0.5f * u.y, -0.5f * u.x);
    float s, co;
    sincospif((float)k * (1.0f / 4096.0f), &s, &co);
    float2 W = make_float2(co, -s);               // e^{-2*pi*i*k/8192}
    float2 WXo = cmul(W, Xo);
    float2 Xk = make_float2(Xe.x + WXo.x, Xe.y + WXo.y);
    float2 Xm = make_float2(Xe.x - WXo.x, -(Xe.y - WXo.y));   // conj(Xe - W*Xo)
    float2 Yk = cmul(Xk, Hk);
    float2 Ym = cmul(Xm, Hm);
    float2 Ye = make_float2(0.5f * (Yk.x + Ym.x), 0.5f * (Yk.y - Ym.y));
    float2 u2 = make_float2(Yk.x - Ym.x, Yk.y + Ym.y);
    float2 Yo = cmulc(make_float2(0.5f * u2.x, 0.5f * u2.y), W);
    Bp[pk] = make_float2(Ye.x - Yo.y, Ye.y + Yo.x);
    Bp[pm] = make_float2(Ye.x + Yo.y, Yo.x - Ye.y);
}

// Prologue: pack H into filter access order (coalesced stores; scattered reads
// stay within one 32KB row -> L1/L2 resident).
__global__ void _permute_H_kernel(const float2 *__restrict__ H2) {
    const int f = blockIdx.x;
    const float2 *Hb = H2 + (size_t)f * 4097;
    float4 *out = g_Hpack + (size_t)f * 2048;
    for (int it = 0; it < 4; it++) {
        int q = it * 512 + threadIdx.x;
        if (q == 0) {
            float2 h0 = __ldg(Hb + 0);
            float2 hN = __ldg(Hb + 4096);
            float2 hM = __ldg(Hb + 2048);
            out[0] = make_float4(h0.x, hN.x, hM.x, hM.y);
        } else {
            int k = ((q & 7) << 8) | (((q >> 3) & 15) << 4) | (q >> 7);
            float2 hk = __ldg(Hb + k);
            float2 hm = __ldg(Hb + 4096 - k);
            out[q] = make_float4(hk.x, hk.y, hm.x, hm.y);
        }
    }
}

__global__ __launch_bounds__(TPB, 1)
void _ScaleFFTFilter_45380624449589_kernel(const float *__restrict__ x,
                                           float *__restrict__ y) {
    extern __shared__ float2 smem_raw[];
    float2 *sm = smem_raw;             // 4 columns * CST
    float2 *tw = smem_raw + 4 * CST;   // padded twiddle table

    const int tid = threadIdx.x;
    const int fg  = blockIdx.x >> 3;   // feature group (0..127)
    const int b   = blockIdx.x & 7;    // batch (0..7)
    const int f0  = fg * 4;

    // twiddle table: tw[m] = e^{-2*pi*i*m/4096}, m < 256
    if (tid < TWN) {
        float s, co;
        sincospif((float)tid * (1.0f / 2048.0f), &s, &co);
        tw[PHYT(tid)] = make_float2(co, -s);
    }
    __syncthreads();

    // ---- fused: global load + pack + first fwd radix-16 pass (Q=256) ----
    {
        const int cc = tid & 3;
        const int j  = tid >> 2;       // 0..255
        const float *xc = x + ((size_t)b * 8192) * 512 + f0 + cc;
        float2 v[16];
        #pragma unroll
        for (int m = 0; m < 16; m++) {
            size_t row = (size_t)2 * (j + m * 256);
            v[m] = make_float2(__ldg(xc + row * 512), __ldg(xc + (row + 1) * 512));
        }
        dft16(v);
        float2 *Bp = sm + cc * CST;
        int p0 = PHYS(j);
        float2 w1 = tw[PHYT(j)];
        Bp[p0] = v[0];
        Bp[p0 + 272] = cmul(v[PERM16(1)], w1);
        float2 w = w1;
        #pragma unroll
        for (int m = 2; m < 16; m++) {
            w = cmul(w, w1);
            Bp[p0 + m * 272] = cmul(v[PERM16(m)], w);
        }
    }
    __syncthreads();

    fwd_pass_mid(sm, tw, tid);

    {   // final forward radix-16 blocks (no twiddles)
        float2 *Bp = sm + (tid >> 8) * CST;
        int p0 = PHYS((tid & 255) * 16);
        float2 v[16];
        #pragma unroll
        for (int j = 0; j < 16; j++) v[j] = Bp[p0 + j];
        dft16(v);
        #pragma unroll
        for (int m = 0; m < 16; m++) Bp[p0 + m] = v[PERM16(m)];
    }
    __syncthreads();

    // ---- unpack -> filter -> repack (digit-reversed domain) ----
    for (int it = 0; it < 8; it++) {
        int idx = it * TPB + tid;      // 0..8191
        int cc = idx >> 11;
        int q  = idx & 2047;
        float2 *Bp = sm + cc * CST;
        float4 hp = __ldg(&g_Hpack[(size_t)(f0 + cc) * 2048 + q]);
        if (q == 0) {
            float2 z0 = Bp[PHYS(0)];
            float Y0 = (z0.x + z0.y) * hp.x;
            float YN = (z0.x - z0.y) * hp.y;
            Bp[PHYS(0)] = make_float2(0.5f * (Y0 + YN), 0.5f * (Y0 - YN));
        } else {
            int k = ((q & 7) << 8) | (((q >> 3) & 15) << 4) | (q >> 7);
            filter_pair(Bp, make_float2(hp.x, hp.y), make_float2(hp.z, hp.w), k);
        }
    }
    if (tid < 4) {   // self-paired bin k = 2048
        float4 hp = __ldg(&g_Hpack[(size_t)(f0 + tid) * 2048]);
        float2 Hm = make_float2(hp.z, hp.w);
        filter_pair(sm + tid * CST, Hm, Hm, 2048);
    }
    __syncthreads();

    {   // first inverse radix-16 blocks (no twiddles)
        float2 *Bp = sm + (tid >> 8) * CST;
        int p0 = PHYS((tid & 255) * 16);
        float2 v[16];
        #pragma unroll
        for (int j = 0; j < 16; j++) {
            float2 u = Bp[p0 + j];
            v[j] = make_float2(u.x, -u.y);
        }
        dft16(v);
        #pragma unroll
        for (int m = 0; m < 16; m++) {
            float2 u = v[PERM16(m)];
            Bp[p0 + m] = make_float2(u.x, -u.y);
        }
    }
    __syncthreads();

    inv_pass_mid(sm, tw, tid);

    // ---- fused: last inverse pass (Q=256) + unpack + global store ----
    {
        const int cc = tid & 3;
        const int j  = tid >> 2;       // 0..255
        float2 *Bp = sm + cc * CST;
        int p0 = PHYS(j);
        float2 w1 = tw[PHYT(j)];
        float2 v[16];
        {
            float2 u = Bp[p0];
            v[0] = make_float2(u.x, -u.y);
        }
        v[1] = cmulc(w1, Bp[p0 + 272]);
        float2 w = w1;
        #pragma unroll
        for (int m = 2; m < 16; m++) {
            w = cmul(w, w1);
            v[m] = cmulc(w, Bp[p0 + m * 272]);
        }
        dft16(v);
        float *yc = y + ((size_t)b * 8192) * 512 + f0 + cc;
        const float SC = 1.0f / 4096.0f;
        #pragma unroll
        for (int m = 0; m < 16; m++) {
            float2 u = v[PERM16(m)];           // result = conj(u)
            size_t row = (size_t)2 * (j + m * 256);
            yc[row * 512]       = u.x * SC;
            yc[(row + 1) * 512] = -u.y * SC;
        }
    }
}

extern "C" void kernel_launch(void* const* d_in, const int* in_sizes, int n_in,
                              void* d_out, int out_size) {
    (void)in_sizes; (void)n_in; (void)out_size;
    const float  *x  = (const float*)d_in[0];
    const float2 *H2 = (const float2*)d_in[1];
    float        *y  = (float*)d_out;

    _permute_H_kernel<<<512, 512>>>(H2);

    const size_t smem_bytes = (size_t)(4 * CST + TWSZ) * sizeof(float2);  // ~141.7 KB
    cudaFuncSetAttribute(_ScaleFFTFilter_45380624449589_kernel,
                         cudaFuncAttributeMaxDynamicSharedMemorySize,
                         (int)smem_bytes);
    _ScaleFFTFilter_45380624449589_kernel<<<1024, TPB, smem_bytes>>>(x, y);
}